// round 1
// baseline (speedup 1.0000x reference)
#include <cuda_runtime.h>
#include <math.h>

#define BB 4
#define LL 8192
#define DDIM 256
#define HH 4
#define NLAYER 4
#define FFD 1024
#define WW 512
#define VV 14
#define DH 64
#define BL (BB*LL)     /* 32768 rows */
#define NBLK (LL/WW)   /* 16 windows per sequence */

// ---------------- scratch (static device globals; no allocations) ----------------
__device__ float g_X [BL*DDIM];   // residual stream
__device__ float g_Hb[BL*DDIM];   // LN output
__device__ float g_Q [BL*DDIM];
__device__ float g_K [BL*DDIM];
__device__ float g_V [BL*DDIM];
__device__ float g_O [BL*DDIM];   // attention output
__device__ float g_F [BL*FFD];    // FFN hidden

// ---------------- embedding gather ----------------
__global__ void embed_kernel(const int* __restrict__ ids, const float* __restrict__ emb,
                             float* __restrict__ x) {
    int i = blockIdx.x * blockDim.x + threadIdx.x;   // float4 index over BL*DDIM/4
    int row = i >> 6;                                 // 64 float4 per row
    int d4  = i & 63;
    int id  = ids[row];
    ((float4*)x)[i] = ((const float4*)emb)[id * 64 + d4];
}

// ---------------- LayerNorm: one warp per row (D=256) ----------------
__global__ void ln_kernel(const float* __restrict__ x, const float* __restrict__ g,
                          const float* __restrict__ b, float* __restrict__ out) {
    int row  = blockIdx.x * 8 + (threadIdx.x >> 5);
    int lane = threadIdx.x & 31;
    const float4* xr = (const float4*)(x + (size_t)row * DDIM);
    float4 v0 = xr[lane];
    float4 v1 = xr[lane + 32];
    float s  = v0.x + v0.y + v0.z + v0.w + v1.x + v1.y + v1.z + v1.w;
    float ss = v0.x*v0.x + v0.y*v0.y + v0.z*v0.z + v0.w*v0.w
             + v1.x*v1.x + v1.y*v1.y + v1.z*v1.z + v1.w*v1.w;
    #pragma unroll
    for (int off = 16; off; off >>= 1) {
        s  += __shfl_xor_sync(0xffffffffu, s,  off);
        ss += __shfl_xor_sync(0xffffffffu, ss, off);
    }
    float mean = s * (1.0f / DDIM);
    float var  = ss * (1.0f / DDIM) - mean * mean;
    float rstd = rsqrtf(var + 1e-5f);
    const float4* gp = (const float4*)g;
    const float4* bp = (const float4*)b;
    float4* op = (float4*)(out + (size_t)row * DDIM);
    float4 g0 = gp[lane], g1 = gp[lane + 32];
    float4 b0 = bp[lane], b1 = bp[lane + 32];
    float4 o0, o1;
    o0.x = (v0.x - mean) * rstd * g0.x + b0.x;
    o0.y = (v0.y - mean) * rstd * g0.y + b0.y;
    o0.z = (v0.z - mean) * rstd * g0.z + b0.z;
    o0.w = (v0.w - mean) * rstd * g0.w + b0.w;
    o1.x = (v1.x - mean) * rstd * g1.x + b1.x;
    o1.y = (v1.y - mean) * rstd * g1.y + b1.y;
    o1.z = (v1.z - mean) * rstd * g1.z + b1.z;
    o1.w = (v1.w - mean) * rstd * g1.w + b1.w;
    op[lane] = o0;
    op[lane + 32] = o1;
}

// ---------------- generic fp32 GEMM: C = act(A@W + bias) [+ Res] ----------------
// BM=128, BN=64, BK=16; 256 threads; 8x4 register blocking.
__device__ __forceinline__ float gelu_tanh(float x) {
    float t = tanhf(0.7978845608028654f * (x + 0.044715f * x * x * x));
    return 0.5f * x * (1.0f + t);
}

template<bool GELU, bool RES>
__global__ void gemm_kernel(const float* __restrict__ A, const float* __restrict__ Bw,
                            const float* __restrict__ bias, const float* __restrict__ Res,
                            float* __restrict__ C, int M, int N, int K) {
    __shared__ float As[16 * 128];
    __shared__ float Bs[16 * 64];
    int tid = threadIdx.x;
    int tx = tid & 15;     // 0..15 -> cols (tx*4)
    int ty = tid >> 4;     // 0..15 -> rows (ty*8)
    int m0 = blockIdx.y * 128;
    int n0 = blockIdx.x * 64;

    float acc[8][4];
    #pragma unroll
    for (int i = 0; i < 8; i++)
        #pragma unroll
        for (int j = 0; j < 4; j++) acc[i][j] = 0.0f;

    for (int k0 = 0; k0 < K; k0 += 16) {
        #pragma unroll
        for (int i = 0; i < 8; i++) {
            int idx = tid + i * 256;          // 0..2047
            int mm = idx >> 4, kk = idx & 15;
            As[kk * 128 + mm] = A[(size_t)(m0 + mm) * K + k0 + kk];
        }
        #pragma unroll
        for (int i = 0; i < 4; i++) {
            int idx = tid + i * 256;          // 0..1023
            int kk = idx >> 6, nn = idx & 63;
            Bs[kk * 64 + nn] = Bw[(size_t)(k0 + kk) * N + n0 + nn];
        }
        __syncthreads();
        #pragma unroll
        for (int kk = 0; kk < 16; kk++) {
            float4 b4 = *(const float4*)&Bs[kk * 64 + tx * 4];
            float4 a0 = *(const float4*)&As[kk * 128 + ty * 8];
            float4 a1 = *(const float4*)&As[kk * 128 + ty * 8 + 4];
            float a[8] = {a0.x, a0.y, a0.z, a0.w, a1.x, a1.y, a1.z, a1.w};
            float bb[4] = {b4.x, b4.y, b4.z, b4.w};
            #pragma unroll
            for (int i = 0; i < 8; i++)
                #pragma unroll
                for (int j = 0; j < 4; j++)
                    acc[i][j] = fmaf(a[i], bb[j], acc[i][j]);
        }
        __syncthreads();
    }

    float4 bv = *(const float4*)&bias[n0 + tx * 4];
    float bias4[4] = {bv.x, bv.y, bv.z, bv.w};
    #pragma unroll
    for (int i = 0; i < 8; i++) {
        int m = m0 + ty * 8 + i;
        size_t off = (size_t)m * N + n0 + tx * 4;
        float v[4];
        #pragma unroll
        for (int j = 0; j < 4; j++) {
            v[j] = acc[i][j] + bias4[j];
            if (GELU) v[j] = gelu_tanh(v[j]);
        }
        if (RES) {
            float4 r = *(const float4*)&Res[off];
            v[0] += r.x; v[1] += r.y; v[2] += r.z; v[3] += r.w;
        }
        float4 o = {v[0], v[1], v[2], v[3]};
        *(float4*)&C[off] = o;
    }
}

// ---------------- fused sliding-window attention with ALiBi ----------------
// Grid: (8 qtiles, H heads, B*NBLK). Block: 256 threads = 8 warps.
// Each warp handles 8 queries; each lane owns output dims (lane, lane+32).
// smem: qsm[64][64], ksmT[64][65] (d-major), vsm[64][64], psm[8][8][64].
#define ATSM_FLOATS (64*64 + 64*65 + 64*64 + 8*8*64)
#define ATSM_BYTES (ATSM_FLOATS * 4)

__global__ void attn_kernel(const float* __restrict__ Q, const float* __restrict__ K,
                            const float* __restrict__ V, float* __restrict__ O) {
    extern __shared__ float sm[];
    float* qsm  = sm;                  // 4096
    float* ksmT = qsm + 64 * 64;       // 64*65 = 4160 (stride 65, d-major)
    float* vsm  = ksmT + 64 * 65;      // 4096
    float* psm  = vsm + 64 * 64;       // 4096

    int qt   = blockIdx.x;             // 0..7
    int head = blockIdx.y;             // 0..3
    int bn   = blockIdx.z;
    int b    = bn / NBLK;
    int nb   = bn % NBLK;
    int q0   = qt * 64;                // query base within window block [0,512)
    int tid  = threadIdx.x;
    int lane = tid & 31;
    int warp = tid >> 5;

    // load 64 queries x 64 dims
    const float* Qbase = Q + ((size_t)(b * LL + nb * WW + q0)) * DDIM + head * DH;
    #pragma unroll
    for (int i = 0; i < 4; i++) {
        int idx = tid + i * 256;       // float4 index, 0..1023
        int qi = idx >> 4, d4 = idx & 15;
        *(float4*)&qsm[qi * 64 + d4 * 4] = *(const float4*)&Qbase[(size_t)qi * DDIM + d4 * 4];
    }

    float m[8], l[8], o0[8], o1[8];
    #pragma unroll
    for (int i = 0; i < 8; i++) { m[i] = -1e30f; l[i] = 0.0f; o0[i] = 0.0f; o1[i] = 0.0f; }

    int lo = q0;
    if (nb == 0) lo = (lo > WW) ? lo : WW;
    int hi = q0 + 63 + WW;                 // <= 1023
    int cmin = lo >> 6, cmax = hi >> 6;

    float slope = exp2f(-2.0f * (float)(head + 1));
    const float scale = 0.125f;
    int kvbase = b * LL + nb * WW - WW;    // sequence row of combined key index 0

    for (int c = cmin; c <= cmax; c++) {
        int kc0 = c * 64;
        __syncthreads();
        // load K (transposed, d-major) and V for this 64-key chunk
        #pragma unroll
        for (int i = 0; i < 4; i++) {
            int idx = tid + i * 256;       // float4 index
            int kk = idx >> 4, d4 = idx & 15;
            size_t gro = ((size_t)(kvbase + kc0 + kk)) * DDIM + head * DH + d4 * 4;
            float4 kv = *(const float4*)&K[gro];
            ksmT[(d4 * 4 + 0) * 65 + kk] = kv.x;
            ksmT[(d4 * 4 + 1) * 65 + kk] = kv.y;
            ksmT[(d4 * 4 + 2) * 65 + kk] = kv.z;
            ksmT[(d4 * 4 + 3) * 65 + kk] = kv.w;
            *(float4*)&vsm[kk * 64 + d4 * 4] = *(const float4*)&V[gro];
        }
        __syncthreads();

        // scores: each lane does keys (lane, lane+32) for warp's 8 queries
        float s0[8], s1[8];
        #pragma unroll
        for (int i = 0; i < 8; i++) { s0[i] = 0.0f; s1[i] = 0.0f; }
        #pragma unroll
        for (int d = 0; d < 64; d += 4) {
            float k0[4], k1[4];
            #pragma unroll
            for (int u = 0; u < 4; u++) {
                k0[u] = ksmT[(d + u) * 65 + lane];
                k1[u] = ksmT[(d + u) * 65 + 32 + lane];
            }
            #pragma unroll
            for (int qi = 0; qi < 8; qi++) {
                float4 qv = *(const float4*)&qsm[(warp * 8 + qi) * 64 + d];
                s0[qi] = fmaf(qv.x, k0[0], fmaf(qv.y, k0[1], fmaf(qv.z, k0[2], fmaf(qv.w, k0[3], s0[qi]))));
                s1[qi] = fmaf(qv.x, k1[0], fmaf(qv.y, k1[1], fmaf(qv.z, k1[2], fmaf(qv.w, k1[3], s1[qi]))));
            }
        }

        int ki0 = kc0 + lane, ki1 = ki0 + 32;
        #pragma unroll
        for (int qi = 0; qi < 8; qi++) {
            int qg = q0 + warp * 8 + qi;
            bool ok0 = (ki0 >= qg) && (ki0 <= qg + WW) && (nb > 0 || ki0 >= WW);
            bool ok1 = (ki1 >= qg) && (ki1 <= qg + WW) && (nb > 0 || ki1 >= WW);
            float d0 = (float)(WW + qg - ki0);
            float d1 = (float)(WW + qg - ki1);
            s0[qi] = ok0 ? (s0[qi] * scale - slope * d0) : -1e30f;
            s1[qi] = ok1 ? (s1[qi] * scale - slope * d1) : -1e30f;
        }

        // online softmax + store p to psm
        #pragma unroll
        for (int qi = 0; qi < 8; qi++) {
            float mx = fmaxf(s0[qi], s1[qi]);
            #pragma unroll
            for (int off = 16; off; off >>= 1)
                mx = fmaxf(mx, __shfl_xor_sync(0xffffffffu, mx, off));
            float mn = fmaxf(m[qi], mx);
            float fac = (m[qi] > -1e29f) ? __expf(m[qi] - mn) : 0.0f;
            float p0 = (s0[qi] > -1e29f) ? __expf(s0[qi] - mn) : 0.0f;
            float p1 = (s1[qi] > -1e29f) ? __expf(s1[qi] - mn) : 0.0f;
            float ps = p0 + p1;
            #pragma unroll
            for (int off = 16; off; off >>= 1)
                ps += __shfl_xor_sync(0xffffffffu, ps, off);
            l[qi] = l[qi] * fac + ps;
            m[qi] = mn;
            o0[qi] *= fac;
            o1[qi] *= fac;
            psm[warp * 512 + qi * 64 + lane] = p0;
            psm[warp * 512 + qi * 64 + lane + 32] = p1;
        }
        __syncwarp();

        // o += p @ v  (lane owns dims lane, lane+32)
        #pragma unroll
        for (int kk = 0; kk < 64; kk += 4) {
            float v0[4], v1[4];
            #pragma unroll
            for (int u = 0; u < 4; u++) {
                v0[u] = vsm[(kk + u) * 64 + lane];
                v1[u] = vsm[(kk + u) * 64 + 32 + lane];
            }
            #pragma unroll
            for (int qi = 0; qi < 8; qi++) {
                float4 pv = *(const float4*)&psm[warp * 512 + qi * 64 + kk];
                o0[qi] = fmaf(pv.x, v0[0], fmaf(pv.y, v0[1], fmaf(pv.z, v0[2], fmaf(pv.w, v0[3], o0[qi]))));
                o1[qi] = fmaf(pv.x, v1[0], fmaf(pv.y, v1[1], fmaf(pv.z, v1[2], fmaf(pv.w, v1[3], o1[qi]))));
            }
        }
        __syncwarp();
    }

    float* Ob = O + ((size_t)(b * LL + nb * WW + q0 + warp * 8)) * DDIM + head * DH;
    #pragma unroll
    for (int qi = 0; qi < 8; qi++) {
        float inv = 1.0f / l[qi];
        Ob[(size_t)qi * DDIM + lane]      = o0[qi] * inv;
        Ob[(size_t)qi * DDIM + lane + 32] = o1[qi] * inv;
    }
}

// ---------------- head: warp per row, N=14 ----------------
__global__ void head_kernel(const float* __restrict__ h, const float* __restrict__ w,
                            float* __restrict__ out) {
    int row  = blockIdx.x * 8 + (threadIdx.x >> 5);
    int lane = threadIdx.x & 31;
    float acc[VV];
    #pragma unroll
    for (int c = 0; c < VV; c++) acc[c] = 0.0f;
    for (int d = lane; d < DDIM; d += 32) {
        float xv = h[(size_t)row * DDIM + d];
        const float* wr = w + d * VV;
        #pragma unroll
        for (int c = 0; c < VV; c++) acc[c] = fmaf(xv, wr[c], acc[c]);
    }
    #pragma unroll
    for (int c = 0; c < VV; c++)
        #pragma unroll
        for (int off = 16; off; off >>= 1)
            acc[c] += __shfl_xor_sync(0xffffffffu, acc[c], off);
    if (lane < VV) out[(size_t)row * VV + lane] = acc[lane];
}

// ---------------- launch ----------------
extern "C" void kernel_launch(void* const* d_in, const int* in_sizes, int n_in,
                              void* d_out, int out_size) {
    const int*   byte_ids = (const int*)  d_in[0];
    const float* embed    = (const float*)d_in[1];
    const float* wq   = (const float*)d_in[2];
    const float* bq   = (const float*)d_in[3];
    const float* wk   = (const float*)d_in[4];
    const float* bk   = (const float*)d_in[5];
    const float* wv   = (const float*)d_in[6];
    const float* bv   = (const float*)d_in[7];
    const float* wo   = (const float*)d_in[8];
    const float* bo   = (const float*)d_in[9];
    const float* ln1g = (const float*)d_in[10];
    const float* ln1b = (const float*)d_in[11];
    const float* ln2g = (const float*)d_in[12];
    const float* ln2b = (const float*)d_in[13];
    const float* w1   = (const float*)d_in[14];
    const float* b1   = (const float*)d_in[15];
    const float* w2   = (const float*)d_in[16];
    const float* b2   = (const float*)d_in[17];
    const float* lnfg = (const float*)d_in[18];
    const float* lnfb = (const float*)d_in[19];
    const float* headw= (const float*)d_in[20];
    float* out = (float*)d_out;

    float *X, *Hb, *Q, *K, *V, *O, *F;
    cudaGetSymbolAddress((void**)&X,  g_X);
    cudaGetSymbolAddress((void**)&Hb, g_Hb);
    cudaGetSymbolAddress((void**)&Q,  g_Q);
    cudaGetSymbolAddress((void**)&K,  g_K);
    cudaGetSymbolAddress((void**)&V,  g_V);
    cudaGetSymbolAddress((void**)&O,  g_O);
    cudaGetSymbolAddress((void**)&F,  g_F);

    cudaFuncSetAttribute(attn_kernel, cudaFuncAttributeMaxDynamicSharedMemorySize, ATSM_BYTES);

    embed_kernel<<<BL * 64 / 256, 256>>>(byte_ids, embed, X);

    dim3 gD(DDIM / 64, BL / 128);    // N=256 GEMMs
    dim3 gF(FFD / 64,  BL / 128);    // N=1024 GEMM
    dim3 gA(8, HH, BB * NBLK);

    for (int l = 0; l < NLAYER; l++) {
        ln_kernel<<<BL / 8, 256>>>(X, ln1g + l * DDIM, ln1b + l * DDIM, Hb);
        gemm_kernel<false, false><<<gD, 256>>>(Hb, wq + (size_t)l * DDIM * DDIM, bq + l * DDIM, nullptr, Q, BL, DDIM, DDIM);
        gemm_kernel<false, false><<<gD, 256>>>(Hb, wk + (size_t)l * DDIM * DDIM, bk + l * DDIM, nullptr, K, BL, DDIM, DDIM);
        gemm_kernel<false, false><<<gD, 256>>>(Hb, wv + (size_t)l * DDIM * DDIM, bv + l * DDIM, nullptr, V, BL, DDIM, DDIM);
        attn_kernel<<<gA, 256, ATSM_BYTES>>>(Q, K, V, O);
        gemm_kernel<false, true ><<<gD, 256>>>(O, wo + (size_t)l * DDIM * DDIM, bo + l * DDIM, X, X, BL, DDIM, DDIM);
        ln_kernel<<<BL / 8, 256>>>(X, ln2g + l * DDIM, ln2b + l * DDIM, Hb);
        gemm_kernel<true,  false><<<gF, 256>>>(Hb, w1 + (size_t)l * DDIM * FFD, b1 + l * FFD, nullptr, F, BL, FFD, DDIM);
        gemm_kernel<false, true ><<<gD, 256>>>(F, w2 + (size_t)l * FFD * DDIM, b2 + l * DDIM, X, X, BL, DDIM, FFD);
    }
    ln_kernel<<<BL / 8, 256>>>(X, lnfg, lnfb, Hb);
    head_kernel<<<BL / 8, 256>>>(Hb, headw, out);
}

// round 3
// speedup vs baseline: 2.3875x; 2.3875x over previous
#include <cuda_runtime.h>
#include <math.h>
#include <stdint.h>

#define BB 4
#define LL 8192
#define DDIM 256
#define HH 4
#define NLAYER 4
#define FFD 1024
#define WW 512
#define VV 14
#define DH 64
#define BL (BB*LL)     /* 32768 rows */
#define NBLK (LL/WW)   /* 16 windows per sequence */

// ---------------- scratch (static device globals; no allocations) ----------------
__device__ float g_X [BL*DDIM];
__device__ float g_Hb[BL*DDIM];
__device__ float g_Q [BL*DDIM];
__device__ float g_K [BL*DDIM];
__device__ float g_V [BL*DDIM];
__device__ float g_O [BL*DDIM];
__device__ float g_F [BL*FFD];

// ---------------- embedding gather ----------------
__global__ void embed_kernel(const int* __restrict__ ids, const float* __restrict__ emb,
                             float* __restrict__ x) {
    int i = blockIdx.x * blockDim.x + threadIdx.x;
    int row = i >> 6;
    int d4  = i & 63;
    int id  = ids[row];
    ((float4*)x)[i] = ((const float4*)emb)[id * 64 + d4];
}

// ---------------- LayerNorm ----------------
__global__ void ln_kernel(const float* __restrict__ x, const float* __restrict__ g,
                          const float* __restrict__ b, float* __restrict__ out) {
    int row  = blockIdx.x * 8 + (threadIdx.x >> 5);
    int lane = threadIdx.x & 31;
    const float4* xr = (const float4*)(x + (size_t)row * DDIM);
    float4 v0 = xr[lane];
    float4 v1 = xr[lane + 32];
    float s  = v0.x + v0.y + v0.z + v0.w + v1.x + v1.y + v1.z + v1.w;
    float ss = v0.x*v0.x + v0.y*v0.y + v0.z*v0.z + v0.w*v0.w
             + v1.x*v1.x + v1.y*v1.y + v1.z*v1.z + v1.w*v1.w;
    #pragma unroll
    for (int off = 16; off; off >>= 1) {
        s  += __shfl_xor_sync(0xffffffffu, s,  off);
        ss += __shfl_xor_sync(0xffffffffu, ss, off);
    }
    float mean = s * (1.0f / DDIM);
    float var  = ss * (1.0f / DDIM) - mean * mean;
    float rstd = rsqrtf(var + 1e-5f);
    const float4* gp = (const float4*)g;
    const float4* bp = (const float4*)b;
    float4* op = (float4*)(out + (size_t)row * DDIM);
    float4 g0 = gp[lane], g1 = gp[lane + 32];
    float4 b0 = bp[lane], b1 = bp[lane + 32];
    float4 o0, o1;
    o0.x = (v0.x - mean) * rstd * g0.x + b0.x;
    o0.y = (v0.y - mean) * rstd * g0.y + b0.y;
    o0.z = (v0.z - mean) * rstd * g0.z + b0.z;
    o0.w = (v0.w - mean) * rstd * g0.w + b0.w;
    o1.x = (v1.x - mean) * rstd * g1.x + b1.x;
    o1.y = (v1.y - mean) * rstd * g1.y + b1.y;
    o1.z = (v1.z - mean) * rstd * g1.z + b1.z;
    o1.w = (v1.w - mean) * rstd * g1.w + b1.w;
    op[lane] = o0;
    op[lane + 32] = o1;
}

__device__ __forceinline__ float gelu_tanh(float x) {
    float t = tanhf(0.7978845608028654f * (x + 0.044715f * x * x * x));
    return 0.5f * x * (1.0f + t);
}

// ================= tf32 mma.sync GEMM: C = act(A@W + bias) [+ Res] =================
// BM=128, BN=128, BK=32; 256 threads = 8 warps (4x2); warp tile 32x64 (2x8 m16n8k8).
#define AS_STRIDE 36
#define BS_STRIDE 136
#define GSM_A (128*AS_STRIDE)          /* floats */
#define GSM_B (32*BS_STRIDE)
#define GSM_BYTES ((GSM_A + GSM_B) * 4)

__device__ __forceinline__ uint32_t f2tf32(float x) {
    uint32_t r;
    asm("cvt.rna.tf32.f32 %0, %1;" : "=r"(r) : "f"(x));
    return r;
}
__device__ __forceinline__ void mma_tf32(float* c, const uint32_t* a, const uint32_t* b) {
    asm volatile(
        "mma.sync.aligned.m16n8k8.row.col.f32.tf32.tf32.f32 "
        "{%0,%1,%2,%3}, {%4,%5,%6,%7}, {%8,%9}, {%0,%1,%2,%3};"
        : "+f"(c[0]), "+f"(c[1]), "+f"(c[2]), "+f"(c[3])
        : "r"(a[0]), "r"(a[1]), "r"(a[2]), "r"(a[3]), "r"(b[0]), "r"(b[1]));
}

template<bool GELU, bool RES>
__global__ void __launch_bounds__(256) gemm_mma(
        const float* __restrict__ A, const float* __restrict__ W,
        const float* __restrict__ bias, const float* __restrict__ Res,
        float* __restrict__ C, int M, int N, int K) {
    extern __shared__ float sm[];
    uint32_t* Asu = (uint32_t*)sm;                 // [128][36] tf32 bits
    uint32_t* Bsu = (uint32_t*)(sm + GSM_A);       // [32][136]
    int tid = threadIdx.x, lane = tid & 31, wid = tid >> 5;
    int wm = wid & 3, wn = wid >> 2;               // warp grid 4 (m) x 2 (n)
    int gid = lane >> 2, tig = lane & 3;
    int m0 = blockIdx.y * 128, n0 = blockIdx.x * 128;

    float acc[2][8][4];
    #pragma unroll
    for (int i = 0; i < 2; i++)
        #pragma unroll
        for (int j = 0; j < 8; j++)
            #pragma unroll
            for (int u = 0; u < 4; u++) acc[i][j][u] = 0.0f;

    for (int k0 = 0; k0 < K; k0 += 32) {
        // A: 128 rows x 32 k (1024 float4s), cvt to tf32, scalar stores stride 36
        #pragma unroll
        for (int i = 0; i < 4; i++) {
            int idx = tid + i * 256;
            int mm = idx >> 3, kq = idx & 7;
            float4 v = *(const float4*)&A[(size_t)(m0 + mm) * K + k0 + kq * 4];
            uint32_t* p = &Asu[mm * AS_STRIDE + kq * 4];
            p[0] = f2tf32(v.x); p[1] = f2tf32(v.y);
            p[2] = f2tf32(v.z); p[3] = f2tf32(v.w);
        }
        // B: 32 k-rows x 128 n, cvt, float4-aligned stores stride 136
        #pragma unroll
        for (int i = 0; i < 4; i++) {
            int idx = tid + i * 256;
            int kk = idx >> 5, nq = idx & 31;
            float4 v = *(const float4*)&W[(size_t)(k0 + kk) * N + n0 + nq * 4];
            uint4 t = {f2tf32(v.x), f2tf32(v.y), f2tf32(v.z), f2tf32(v.w)};
            *(uint4*)&Bsu[kk * BS_STRIDE + nq * 4] = t;
        }
        __syncthreads();

        #pragma unroll
        for (int ks = 0; ks < 4; ks++) {
            int kb = ks * 8;
            uint32_t afr[2][4];
            #pragma unroll
            for (int tm = 0; tm < 2; tm++) {
                int row = wm * 32 + tm * 16 + gid;
                afr[tm][0] = Asu[row * AS_STRIDE + kb + tig];
                afr[tm][1] = Asu[(row + 8) * AS_STRIDE + kb + tig];
                afr[tm][2] = Asu[row * AS_STRIDE + kb + tig + 4];
                afr[tm][3] = Asu[(row + 8) * AS_STRIDE + kb + tig + 4];
            }
            uint32_t bfr[8][2];
            #pragma unroll
            for (int tn = 0; tn < 8; tn++) {
                int col = wn * 64 + tn * 8 + gid;
                bfr[tn][0] = Bsu[(kb + tig) * BS_STRIDE + col];
                bfr[tn][1] = Bsu[(kb + tig + 4) * BS_STRIDE + col];
            }
            #pragma unroll
            for (int tm = 0; tm < 2; tm++)
                #pragma unroll
                for (int tn = 0; tn < 8; tn++)
                    mma_tf32(acc[tm][tn], afr[tm], bfr[tn]);
        }
        __syncthreads();
    }

    // epilogue
    #pragma unroll
    for (int tm = 0; tm < 2; tm++) {
        int row = m0 + wm * 32 + tm * 16 + gid;
        #pragma unroll
        for (int tn = 0; tn < 8; tn++) {
            int col = n0 + wn * 64 + tn * 8 + tig * 2;
            float b0 = bias[col], b1 = bias[col + 1];
            #pragma unroll
            for (int half = 0; half < 2; half++) {
                int r = row + half * 8;
                float v0 = acc[tm][tn][half * 2 + 0] + b0;
                float v1 = acc[tm][tn][half * 2 + 1] + b1;
                if (GELU) { v0 = gelu_tanh(v0); v1 = gelu_tanh(v1); }
                size_t off = (size_t)r * N + col;
                if (RES) {
                    float2 rr = *(const float2*)&Res[off];
                    v0 += rr.x; v1 += rr.y;
                }
                float2 o = {v0, v1};
                *(float2*)&C[off] = o;
            }
        }
    }
}

// ---------------- fused sliding-window attention with ALiBi ----------------
#define ATSM_FLOATS (64*64 + 64*65 + 64*64 + 8*8*64)
#define ATSM_BYTES (ATSM_FLOATS * 4)

__global__ void attn_kernel(const float* __restrict__ Q, const float* __restrict__ K,
                            const float* __restrict__ V, float* __restrict__ O) {
    extern __shared__ float sm[];
    float* qsm  = sm;
    float* ksmT = qsm + 64 * 64;
    float* vsm  = ksmT + 64 * 65;
    float* psm  = vsm + 64 * 64;

    int qt   = blockIdx.x;
    int head = blockIdx.y;
    int bn   = blockIdx.z;
    int b    = bn / NBLK;
    int nb   = bn % NBLK;
    int q0   = qt * 64;
    int tid  = threadIdx.x;
    int lane = tid & 31;
    int warp = tid >> 5;

    const float* Qbase = Q + ((size_t)(b * LL + nb * WW + q0)) * DDIM + head * DH;
    #pragma unroll
    for (int i = 0; i < 4; i++) {
        int idx = tid + i * 256;
        int qi = idx >> 4, d4 = idx & 15;
        *(float4*)&qsm[qi * 64 + d4 * 4] = *(const float4*)&Qbase[(size_t)qi * DDIM + d4 * 4];
    }

    float m[8], l[8], o0[8], o1[8];
    #pragma unroll
    for (int i = 0; i < 8; i++) { m[i] = -1e30f; l[i] = 0.0f; o0[i] = 0.0f; o1[i] = 0.0f; }

    int lo = q0;
    if (nb == 0) lo = (lo > WW) ? lo : WW;
    int hi = q0 + 63 + WW;
    int cmin = lo >> 6, cmax = hi >> 6;

    float slope = exp2f(-2.0f * (float)(head + 1));
    const float scale = 0.125f;
    int kvbase = b * LL + nb * WW - WW;

    for (int c = cmin; c <= cmax; c++) {
        int kc0 = c * 64;
        __syncthreads();
        #pragma unroll
        for (int i = 0; i < 4; i++) {
            int idx = tid + i * 256;
            int kk = idx >> 4, d4 = idx & 15;
            size_t gro = ((size_t)(kvbase + kc0 + kk)) * DDIM + head * DH + d4 * 4;
            float4 kv = *(const float4*)&K[gro];
            ksmT[(d4 * 4 + 0) * 65 + kk] = kv.x;
            ksmT[(d4 * 4 + 1) * 65 + kk] = kv.y;
            ksmT[(d4 * 4 + 2) * 65 + kk] = kv.z;
            ksmT[(d4 * 4 + 3) * 65 + kk] = kv.w;
            *(float4*)&vsm[kk * 64 + d4 * 4] = *(const float4*)&V[gro];
        }
        __syncthreads();

        float s0[8], s1[8];
        #pragma unroll
        for (int i = 0; i < 8; i++) { s0[i] = 0.0f; s1[i] = 0.0f; }
        #pragma unroll
        for (int d = 0; d < 64; d += 4) {
            float k0[4], k1[4];
            #pragma unroll
            for (int u = 0; u < 4; u++) {
                k0[u] = ksmT[(d + u) * 65 + lane];
                k1[u] = ksmT[(d + u) * 65 + 32 + lane];
            }
            #pragma unroll
            for (int qi = 0; qi < 8; qi++) {
                float4 qv = *(const float4*)&qsm[(warp * 8 + qi) * 64 + d];
                s0[qi] = fmaf(qv.x, k0[0], fmaf(qv.y, k0[1], fmaf(qv.z, k0[2], fmaf(qv.w, k0[3], s0[qi]))));
                s1[qi] = fmaf(qv.x, k1[0], fmaf(qv.y, k1[1], fmaf(qv.z, k1[2], fmaf(qv.w, k1[3], s1[qi]))));
            }
        }

        int ki0 = kc0 + lane, ki1 = ki0 + 32;
        #pragma unroll
        for (int qi = 0; qi < 8; qi++) {
            int qg = q0 + warp * 8 + qi;
            bool ok0 = (ki0 >= qg) && (ki0 <= qg + WW) && (nb > 0 || ki0 >= WW);
            bool ok1 = (ki1 >= qg) && (ki1 <= qg + WW) && (nb > 0 || ki1 >= WW);
            float d0 = (float)(WW + qg - ki0);
            float d1 = (float)(WW + qg - ki1);
            s0[qi] = ok0 ? (s0[qi] * scale - slope * d0) : -1e30f;
            s1[qi] = ok1 ? (s1[qi] * scale - slope * d1) : -1e30f;
        }

        #pragma unroll
        for (int qi = 0; qi < 8; qi++) {
            float mx = fmaxf(s0[qi], s1[qi]);
            #pragma unroll
            for (int off = 16; off; off >>= 1)
                mx = fmaxf(mx, __shfl_xor_sync(0xffffffffu, mx, off));
            float mn = fmaxf(m[qi], mx);
            float fac = (m[qi] > -1e29f) ? __expf(m[qi] - mn) : 0.0f;
            float p0 = (s0[qi] > -1e29f) ? __expf(s0[qi] - mn) : 0.0f;
            float p1 = (s1[qi] > -1e29f) ? __expf(s1[qi] - mn) : 0.0f;
            float ps = p0 + p1;
            #pragma unroll
            for (int off = 16; off; off >>= 1)
                ps += __shfl_xor_sync(0xffffffffu, ps, off);
            l[qi] = l[qi] * fac + ps;
            m[qi] = mn;
            o0[qi] *= fac;
            o1[qi] *= fac;
            psm[warp * 512 + qi * 64 + lane] = p0;
            psm[warp * 512 + qi * 64 + lane + 32] = p1;
        }
        __syncwarp();

        #pragma unroll
        for (int kk = 0; kk < 64; kk += 4) {
            float v0[4], v1[4];
            #pragma unroll
            for (int u = 0; u < 4; u++) {
                v0[u] = vsm[(kk + u) * 64 + lane];
                v1[u] = vsm[(kk + u) * 64 + 32 + lane];
            }
            #pragma unroll
            for (int qi = 0; qi < 8; qi++) {
                float4 pv = *(const float4*)&psm[warp * 512 + qi * 64 + kk];
                o0[qi] = fmaf(pv.x, v0[0], fmaf(pv.y, v0[1], fmaf(pv.z, v0[2], fmaf(pv.w, v0[3], o0[qi]))));
                o1[qi] = fmaf(pv.x, v1[0], fmaf(pv.y, v1[1], fmaf(pv.z, v1[2], fmaf(pv.w, v1[3], o1[qi]))));
            }
        }
        __syncwarp();
    }

    float* Ob = O + ((size_t)(b * LL + nb * WW + q0 + warp * 8)) * DDIM + head * DH;
    #pragma unroll
    for (int qi = 0; qi < 8; qi++) {
        float inv = 1.0f / l[qi];
        Ob[(size_t)qi * DDIM + lane]      = o0[qi] * inv;
        Ob[(size_t)qi * DDIM + lane + 32] = o1[qi] * inv;
    }
}

// ---------------- head: warp per row, N=14 ----------------
__global__ void head_kernel(const float* __restrict__ h, const float* __restrict__ w,
                            float* __restrict__ out) {
    int row  = blockIdx.x * 8 + (threadIdx.x >> 5);
    int lane = threadIdx.x & 31;
    float acc[VV];
    #pragma unroll
    for (int c = 0; c < VV; c++) acc[c] = 0.0f;
    for (int d = lane; d < DDIM; d += 32) {
        float xv = h[(size_t)row * DDIM + d];
        const float* wr = w + d * VV;
        #pragma unroll
        for (int c = 0; c < VV; c++) acc[c] = fmaf(xv, wr[c], acc[c]);
    }
    #pragma unroll
    for (int c = 0; c < VV; c++)
        #pragma unroll
        for (int off = 16; off; off >>= 1)
            acc[c] += __shfl_xor_sync(0xffffffffu, acc[c], off);
    if (lane < VV) out[(size_t)row * VV + lane] = acc[lane];
}

// ---------------- launch ----------------
extern "C" void kernel_launch(void* const* d_in, const int* in_sizes, int n_in,
                              void* d_out, int out_size) {
    const int*   byte_ids = (const int*)  d_in[0];
    const float* embed    = (const float*)d_in[1];
    const float* wq   = (const float*)d_in[2];
    const float* bq   = (const float*)d_in[3];
    const float* wk   = (const float*)d_in[4];
    const float* bk   = (const float*)d_in[5];
    const float* wv   = (const float*)d_in[6];
    const float* bv   = (const float*)d_in[7];
    const float* wo   = (const float*)d_in[8];
    const float* bo   = (const float*)d_in[9];
    const float* ln1g = (const float*)d_in[10];
    const float* ln1b = (const float*)d_in[11];
    const float* ln2g = (const float*)d_in[12];
    const float* ln2b = (const float*)d_in[13];
    const float* w1   = (const float*)d_in[14];
    const float* b1   = (const float*)d_in[15];
    const float* w2   = (const float*)d_in[16];
    const float* b2   = (const float*)d_in[17];
    const float* lnfg = (const float*)d_in[18];
    const float* lnfb = (const float*)d_in[19];
    const float* headw= (const float*)d_in[20];
    float* out = (float*)d_out;

    float *X, *Hb, *Q, *K, *V, *O, *F;
    cudaGetSymbolAddress((void**)&X,  g_X);
    cudaGetSymbolAddress((void**)&Hb, g_Hb);
    cudaGetSymbolAddress((void**)&Q,  g_Q);
    cudaGetSymbolAddress((void**)&K,  g_K);
    cudaGetSymbolAddress((void**)&V,  g_V);
    cudaGetSymbolAddress((void**)&O,  g_O);
    cudaGetSymbolAddress((void**)&F,  g_F);

    cudaFuncSetAttribute(attn_kernel, cudaFuncAttributeMaxDynamicSharedMemorySize, ATSM_BYTES);

    embed_kernel<<<BL * 64 / 256, 256>>>(byte_ids, embed, X);

    dim3 gD(DDIM / 128, BL / 128);   // (2, 256)
    dim3 gF(FFD / 128,  BL / 128);   // (8, 256)
    dim3 gA(8, HH, BB * NBLK);
    const size_t SMB = GSM_BYTES;

    for (int l = 0; l < NLAYER; l++) {
        ln_kernel<<<BL / 8, 256>>>(X, ln1g + l * DDIM, ln1b + l * DDIM, Hb);
        gemm_mma<false, false><<<gD, 256, SMB>>>(Hb, wq + (size_t)l * DDIM * DDIM, bq + l * DDIM, nullptr, Q, BL, DDIM, DDIM);
        gemm_mma<false, false><<<gD, 256, SMB>>>(Hb, wk + (size_t)l * DDIM * DDIM, bk + l * DDIM, nullptr, K, BL, DDIM, DDIM);
        gemm_mma<false, false><<<gD, 256, SMB>>>(Hb, wv + (size_t)l * DDIM * DDIM, bv + l * DDIM, nullptr, V, BL, DDIM, DDIM);
        attn_kernel<<<gA, 256, ATSM_BYTES>>>(Q, K, V, O);
        gemm_mma<false, true ><<<gD, 256, SMB>>>(O, wo + (size_t)l * DDIM * DDIM, bo + l * DDIM, X, X, BL, DDIM, DDIM);
        ln_kernel<<<BL / 8, 256>>>(X, ln2g + l * DDIM, ln2b + l * DDIM, Hb);
        gemm_mma<true,  false><<<gF, 256, SMB>>>(Hb, w1 + (size_t)l * DDIM * FFD, b1 + l * FFD, nullptr, F, BL, FFD, DDIM);
        gemm_mma<false, true ><<<gD, 256, SMB>>>(F, w2 + (size_t)l * FFD * DDIM, b2 + l * DDIM, X, X, BL, DDIM, FFD);
    }
    ln_kernel<<<BL / 8, 256>>>(X, lnfg, lnfb, Hb);
    head_kernel<<<BL / 8, 256>>>(Hb, headw, out);
}